// round 10
// baseline (speedup 1.0000x reference)
#include <cuda_runtime.h>
#include <cuda_bf16.h>

// Problem constants
#define S 8192
#define D 1024
#define E 64
#define CAP 128
#define SHIFT 4096
static const long long SEC = (long long)S * E * CAP;   // 67108864

#define GEMM_BLOCKS 128
#define ZERO_BLOCKS 1024
#define TB 64                        // tail blocks (all resident: 64 << 148)

// ---------------- scratch (device globals) ----------------------------------
__device__ int   g_beste[S];
__device__ float g_gmax[S];
__device__ int   g_expert_at_p[S];
__device__ int   g_token_at_p[S];
__device__ int   g_hist[S];          // [128 chunks][64 experts]; zeroed each call
__device__ int   g_choff[S];
__device__ float g_me_part[GEMM_BLOCKS * E];
__device__ int   g_cnt_part[GEMM_BLOCKS * E];
__device__ unsigned g_c1, g_c2, g_c3, g_c4;   // spin barriers; self-resetting

// ---------------------------------------------------------------------------
// K1: blocks 0..127 : GEMM (64 tokens x 64 experts) + softmax epilogue
//     blocks 128..  : grid-stride zero-fill of the whole output (proven)
// ---------------------------------------------------------------------------
__global__ void k1_fused(const float* __restrict__ x,
                         const float* __restrict__ w,
                         float* __restrict__ out, long long out_size) {
    const int tid = threadIdx.x;

    if (blockIdx.x < GEMM_BLOCKS) {
        __shared__ float sbuf[64 * 65];           // As/Bs alias + logits L[64][65]
        float (*As)[64] = (float(*)[64])sbuf;          // [32][64]
        float (*Bs)[64] = (float(*)[64])(sbuf + 2048); // [32][64]
        __shared__ float smax[64], sinv[64];
        __shared__ int   scnt[E];

        const int m0 = blockIdx.x * 64;
        const int tx = tid & 15;
        const int ty = tid >> 4;
        float acc[4][4];
        #pragma unroll
        for (int i = 0; i < 4; i++)
            #pragma unroll
            for (int j = 0; j < 4; j++) acc[i][j] = 0.0f;

        for (int k0 = 0; k0 < D; k0 += 32) {
            #pragma unroll
            for (int r = 0; r < 8; r++) {
                int l  = tid + r * 256;
                int mm = l & 63;
                int kk = l >> 6;
                As[kk][mm] = x[(long long)(m0 + mm) * D + k0 + kk];
                Bs[kk][mm] = w[(long long)mm * D + k0 + kk];
            }
            __syncthreads();
            #pragma unroll
            for (int kk = 0; kk < 32; kk++) {
                const float4 a = *(const float4*)(&As[kk][ty * 4]);
                const float4 b = *(const float4*)(&Bs[kk][tx * 4]);
                float av[4] = {a.x, a.y, a.z, a.w};
                float bv[4] = {b.x, b.y, b.z, b.w};
                #pragma unroll
                for (int i = 0; i < 4; i++)
                    #pragma unroll
                    for (int j = 0; j < 4; j++)
                        acc[i][j] += av[i] * bv[j];
            }
            __syncthreads();
        }

        float* L = sbuf;                           // [64][65] padded
        #pragma unroll
        for (int i = 0; i < 4; i++)
            #pragma unroll
            for (int j = 0; j < 4; j++)
                L[(ty * 4 + i) * 65 + tx * 4 + j] = acc[i][j];
        if (tid < E) scnt[tid] = 0;
        __syncthreads();

        if (tid < 64) {
            const int t = tid;
            float bv = L[t * 65];
            int   bi = 0;
            #pragma unroll 8
            for (int e = 1; e < E; e++) {
                float v = L[t * 65 + e];
                if (v > bv) { bv = v; bi = e; }
            }
            float s = 0.0f;
            #pragma unroll 8
            for (int e = 0; e < E; e++) s += expf(L[t * 65 + e] - bv);
            float inv = 1.0f / s;
            smax[t] = bv;
            sinv[t] = inv;
            g_beste[m0 + t] = bi;
            g_gmax[m0 + t]  = inv;                 // max gate = 1/sum
            atomicAdd(&scnt[bi], 1);
        }
        __syncthreads();
        if (tid < E) {
            const int e = tid;
            float me = 0.0f;
            #pragma unroll 8
            for (int t = 0; t < 64; t++)
                me += expf(L[t * 65 + e] - smax[t]) * sinv[t];
            g_me_part[blockIdx.x * E + e]  = me;
            g_cnt_part[blockIdx.x * E + e] = scnt[e];
        }
    } else {
        // ---- zero-fill the whole output buffer (poisoned to 0xAA) ----
        long long n4 = out_size >> 2;
        float4* o4 = (float4*)out;
        const float4 z = make_float4(0.f, 0.f, 0.f, 0.f);
        long long idx    = (long long)(blockIdx.x - GEMM_BLOCKS) * blockDim.x + tid;
        long long stride = (long long)ZERO_BLOCKS * blockDim.x;
        for (; idx < n4; idx += stride) o4[idx] = z;
        if (blockIdx.x == GEMM_BLOCKS) {
            for (long long i = (n4 << 2) + tid; i < out_size; i += blockDim.x)
                out[i] = 0.0f;
        }
    }
}

// ---------------------------------------------------------------------------
// kT: entire routing tail in ONE launch (64 blocks x 1024 threads, post-fill)
//   phase1: per-block rank of 128 tokens vs all 8192 gmax (smem resident)
//   b1 -> positions+hist atomics -> b2 -> prefix(block0) | finalize(block1)
//   -> b3 -> ballot scatter (2 chunks/block)
// ---------------------------------------------------------------------------
__global__ void __launch_bounds__(1024)
kT(float* __restrict__ out) {
    __shared__ float sh[S];              // 32 KB: all gmax
    __shared__ int   sranks[128];
    __shared__ int   spart[4 * 64];
    __shared__ int   h0[2 * 64];
    const int b   = blockIdx.x;
    const int tid = threadIdx.x;

    // zero own hist slice (before barrier 1)
    if (tid < 128) g_hist[b * 128 + tid] = 0;
    // stage all gmax
    for (int i = tid; i < S; i += 1024) sh[i] = g_gmax[i];
    __syncthreads();

    // ---- phase 1: stable rank (counting) for tokens [b*128, b*128+128) ----
    {
        const int tok  = tid >> 3;           // 0..127
        const int part = tid & 7;            // 8 u-slices of 1024
        const int tg   = b * 128 + tok;
        const float gt = sh[tg];
        int cnt = 0;
        const int base = part * 1024;
        #pragma unroll 8
        for (int j = 0; j < 1024; j++) {
            int u = base + j;
            float v = sh[u];
            cnt += (u < tg) ? (v >= gt) : (v > gt);
        }
        cnt += __shfl_down_sync(0xffffffffu, cnt, 4, 8);
        cnt += __shfl_down_sync(0xffffffffu, cnt, 2, 8);
        cnt += __shfl_down_sync(0xffffffffu, cnt, 1, 8);
        if (part == 0) sranks[tok] = cnt;
    }
    __threadfence();                          // hist zeroing visible
    __syncthreads();

    // ---- barrier 1: all hist slices zeroed, ranks local ----
    if (tid == 0) {
        atomicAdd(&g_c1, 1u);
        while (atomicAdd(&g_c1, 0u) < (unsigned)TB) {}
    }
    __syncthreads();

    // ---- phase 2: positions (roll) + global histogram ----
    if (tid < 128) {
        const int t = b * 128 + tid;
        const int p = (sranks[tid] + SHIFT) & (S - 1);
        const int e = g_beste[t];
        g_expert_at_p[p] = e;
        g_token_at_p[p]  = t;
        atomicAdd(&g_hist[(p >> 6) * E + e], 1);
    }
    __threadfence();
    __syncthreads();
    if (tid == 0) atomicAdd(&g_c2, 1u);

    // ---- phase 3: block 0 prefix; block 1 finalize (independent) ----
    if (b == 0) {
        if (tid == 0) { while (atomicAdd(&g_c2, 0u) < (unsigned)TB) {} }
        __syncthreads();
        // per-expert exclusive prefix over 128 chunks (batched loads)
        const int e = tid & 63, q = tid >> 6 & 3;  // use first 256 threads
        if (tid < 256) {
            int v[32];
            int sum = 0;
            #pragma unroll
            for (int i = 0; i < 32; i++) {
                v[i] = __ldcg(&g_hist[((q * 32 + i) << 6) + e]);
                sum += v[i];
            }
            spart[q * 64 + e] = sum;
            __syncwarp();
            // need all 4 quarters' partials: block-level sync below
            // (store v to recompute after sync)
            // We re-do with a __syncthreads-safe structure:
            // stash v in registers; sync; then scan.
            int dummy = 0; (void)dummy;
            // fallthrough handled after __syncthreads
            // store v into smem is too big; recompute run after sync:
            // (done below)
            // mark done
            // NOTE: code continues after barrier below
            // -- we place the scan after __syncthreads() outside this if --
            // To keep v alive, do the scan here after a block sync:
            // (split with named barrier not needed: use __syncthreads via all threads)
            // see below
            // placeholder
            ;
            // we cannot __syncthreads inside divergent branch; so write partial
            // sums and ALSO write v to g_choff temporarily? Simpler: recompute.
        }
        __syncthreads();                       // all 1024 threads reach here
        if (tid < 256) {
            int run = 0;
            for (int qq = 0; qq < q; qq++) run += spart[qq * 64 + e];
            #pragma unroll
            for (int i = 0; i < 32; i++) {
                int idx = ((q * 32 + i) << 6) + e;
                int v = __ldcg(&g_hist[idx]);  // L2-hot, cheap reload
                g_choff[idx] = run;
                run += v;
            }
        }
        __threadfence();
        __syncthreads();
        if (tid == 0) {
            atomicAdd(&g_c3, 1u);
            g_c1 = 0;                          // safe: all passed barrier 1
        }
    } else {
        if (b == 1) {
            // finalize: tree reduce of 128x64 partials
            __shared__ float sme[16][64];
            __shared__ int   scn[16][64];
            const int e = tid & 63;
            const int g = tid >> 6;            // 16 groups of 8 gemm blocks
            float me = 0.0f;
            int   c  = 0;
            #pragma unroll
            for (int i = 0; i < 8; i++) {
                int bb = g * 8 + i;
                me += g_me_part[bb * E + e];
                c  += g_cnt_part[bb * E + e];
            }
            sme[g][e] = me;
            scn[g][e] = c;
            __syncthreads();
            const float inv = 1.0f / (float)S;
            if (tid < E) {
                float m = 0.0f;
                int  cc = 0;
                #pragma unroll
                for (int gg = 0; gg < 16; gg++) { m += sme[gg][tid]; cc += scn[gg][tid]; }
                sme[0][tid] = (m * inv) * ((float)cc * inv);
                scn[0][tid] = cc;
                out[1LL + 2LL * SEC + tid] = (float)cc;
            }
            __syncthreads();
            if (tid == 0) {
                float sum = 0.0f;
                int dropped = 0;
                for (int k = 0; k < E; k++) {
                    sum += sme[0][k];
                    int d = scn[0][k] - CAP;
                    if (d > 0) dropped += d;
                }
                out[0] = sum * (float)E * 0.01f;
                out[1LL + 2LL * SEC + E] = (float)dropped * inv;
            }
        }
        if (tid == 0) atomicAdd(&g_c3, 1u);
    }

    // ---- barrier 3: prefix done ----
    if (tid == 0) { while (atomicAdd(&g_c3, 0u) < (unsigned)TB) {} }
    __syncthreads();
    if (b == 0 && tid == 0) g_c2 = 0;          // safe: all passed barrier 2

    // ---- phase 4: ballot scatter, chunks 2b and 2b+1 ----
    if (tid < 128) {
        const int chunkL = tid >> 6;           // 0/1
        const int lane   = tid & 31;
        const int half   = (tid >> 5) & 1;
        const int gchunk = b * 2 + chunkL;
        const int p = gchunk * 64 + (tid & 63);
        const int e = g_expert_at_p[p];
        const int t = g_token_at_p[p];
        h0[tid] = 0;
        __syncwarp();
        unsigned mask = __match_any_sync(0xffffffffu, e);
        int below = __popc(mask & ((1u << lane) - 1u));
        if (half == 0 && lane == (int)(__ffs(mask) - 1))
            h0[chunkL * 64 + e] = __popc(mask);
        __syncthreads();
        int c = below + (half ? h0[chunkL * 64 + e] : 0);
        const int loc = g_choff[gchunk * E + e] + c;
        if (loc < CAP) {
            long long base = 1LL + ((long long)t * E + e) * CAP + loc;
            out[base]       = sh[t];           // combine weight = gmax (smem)
            out[base + SEC] = 1.0f;
        }
    } else {
        __syncthreads();                       // match phase-4 syncthreads
    }

    // ---- completion: last block resets remaining counters ----
    __syncthreads();
    if (tid == 0) {
        unsigned done = atomicAdd(&g_c4, 1u);
        if (done == (unsigned)(TB - 1)) { g_c3 = 0; g_c4 = 0; }
    }
}

// ---------------------------------------------------------------------------
extern "C" void kernel_launch(void* const* d_in, const int* in_sizes, int n_in,
                              void* d_out, int out_size) {
    const float* x = (const float*)d_in[0];   // [S, D]
    const float* w = (const float*)d_in[1];   // [E, D]
    float* out = (float*)d_out;
    long long osz = (long long)out_size;

    k1_fused<<<GEMM_BLOCKS + ZERO_BLOCKS, 256>>>(x, w, out, osz);
    kT<<<TB, 1024>>>(out);
}

// round 11
// speedup vs baseline: 1.4035x; 1.4035x over previous
#include <cuda_runtime.h>
#include <cuda_bf16.h>

// Problem constants
#define S 8192
#define D 1024
#define E 64
#define CAP 128
#define SHIFT 4096
static const long long SEC = (long long)S * E * CAP;   // 67108864

#define GEMM_BLOCKS 128
#define ZERO_BLOCKS 1024

// ---------------- scratch (device globals) ----------------------------------
__device__ int   g_beste[S];
__device__ float g_gmax[S];
__device__ int   g_expert_at_p[S];
__device__ int   g_token_at_p[S];
__device__ int   g_hist[S];          // [128 chunks][64 experts]; zeroed in k1
__device__ int   g_choff[S];
__device__ float g_me_part[GEMM_BLOCKS * E];
__device__ int   g_cnt_part[GEMM_BLOCKS * E];
__device__ unsigned g_done, g_c4;    // k3 flag + reset counter (self-reset)

// ---------------------------------------------------------------------------
// K1: blocks 0..127 : GEMM (64 tokens x 64 experts) + softmax epilogue
//     blocks 128..  : grid-stride zero-fill of the whole output (proven)
// ---------------------------------------------------------------------------
__global__ void k1_fused(const float* __restrict__ x,
                         const float* __restrict__ w,
                         float* __restrict__ out, long long out_size) {
    const int tid = threadIdx.x;

    if (blockIdx.x < GEMM_BLOCKS) {
        __shared__ float sbuf[64 * 65];           // As/Bs alias + logits L[64][65]
        float (*As)[64] = (float(*)[64])sbuf;          // [32][64]
        float (*Bs)[64] = (float(*)[64])(sbuf + 2048); // [32][64]
        __shared__ float smax[64], sinv[64];
        __shared__ int   scnt[E];

        const int m0 = blockIdx.x * 64;
        const int tx = tid & 15;
        const int ty = tid >> 4;
        float acc[4][4];
        #pragma unroll
        for (int i = 0; i < 4; i++)
            #pragma unroll
            for (int j = 0; j < 4; j++) acc[i][j] = 0.0f;

        for (int k0 = 0; k0 < D; k0 += 32) {
            #pragma unroll
            for (int r = 0; r < 8; r++) {
                int l  = tid + r * 256;
                int mm = l & 63;
                int kk = l >> 6;
                As[kk][mm] = x[(long long)(m0 + mm) * D + k0 + kk];
                Bs[kk][mm] = w[(long long)mm * D + k0 + kk];
            }
            __syncthreads();
            #pragma unroll
            for (int kk = 0; kk < 32; kk++) {
                const float4 a = *(const float4*)(&As[kk][ty * 4]);
                const float4 b = *(const float4*)(&Bs[kk][tx * 4]);
                float av[4] = {a.x, a.y, a.z, a.w};
                float bv[4] = {b.x, b.y, b.z, b.w};
                #pragma unroll
                for (int i = 0; i < 4; i++)
                    #pragma unroll
                    for (int j = 0; j < 4; j++)
                        acc[i][j] += av[i] * bv[j];
            }
            __syncthreads();
        }

        float* L = sbuf;                           // [64][65] padded
        #pragma unroll
        for (int i = 0; i < 4; i++)
            #pragma unroll
            for (int j = 0; j < 4; j++)
                L[(ty * 4 + i) * 65 + tx * 4 + j] = acc[i][j];
        if (tid < E) scnt[tid] = 0;
        __syncthreads();

        if (tid < 64) {
            const int t = tid;
            float bv = L[t * 65];
            int   bi = 0;
            #pragma unroll 8
            for (int e = 1; e < E; e++) {
                float v = L[t * 65 + e];
                if (v > bv) { bv = v; bi = e; }
            }
            float s = 0.0f;
            #pragma unroll 8
            for (int e = 0; e < E; e++) s += expf(L[t * 65 + e] - bv);
            float inv = 1.0f / s;
            smax[t] = bv;
            sinv[t] = inv;
            g_beste[m0 + t] = bi;
            g_gmax[m0 + t]  = inv;                 // max gate = 1/sum
            atomicAdd(&scnt[bi], 1);
        }
        __syncthreads();
        if (tid < E) {
            const int e = tid;
            float me = 0.0f;
            #pragma unroll 8
            for (int t = 0; t < 64; t++)
                me += expf(L[t * 65 + e] - smax[t]) * sinv[t];
            g_me_part[blockIdx.x * E + e]  = me;
            g_cnt_part[blockIdx.x * E + e] = scnt[e];
        }
    } else {
        // ---- zero-fill the whole output buffer (poisoned to 0xAA) ----
        long long n4 = out_size >> 2;
        float4* o4 = (float4*)out;
        const float4 z = make_float4(0.f, 0.f, 0.f, 0.f);
        long long idx    = (long long)(blockIdx.x - GEMM_BLOCKS) * blockDim.x + tid;
        long long stride = (long long)ZERO_BLOCKS * blockDim.x;
        for (; idx < n4; idx += stride) o4[idx] = z;
        if (blockIdx.x == GEMM_BLOCKS) {
            for (long long i = (n4 << 2) + tid; i < out_size; i += blockDim.x)
                out[i] = 0.0f;
            for (int i = tid; i < S; i += blockDim.x) g_hist[i] = 0;  // pre-zero hist
        }
    }
}

// ---------------------------------------------------------------------------
// K2: rank + position + histogram, full-chip parallel.
//   128 blocks x 256 thr; block b handles tokens [b*64, b*64+64).
//   part = tid>>6 (4 slices of 2048), token = tid&63 -> warp-uniform slice
//   (broadcast LDS, no bank conflicts).
//   rank(t) = #{u: g[u] > g[t]} + #{u < t: g[u] == g[t]}   (exact stable rank)
// ---------------------------------------------------------------------------
__global__ void __launch_bounds__(256) k2_rankpos() {
    __shared__ float sh[S];              // 32 KB: all gmax
    __shared__ int   spcnt[4][65];
    const int tid = threadIdx.x;
    const int b   = blockIdx.x;
    for (int i = tid; i < S; i += 256) sh[i] = g_gmax[i];
    __syncthreads();

    const int tok  = tid & 63;
    const int part = tid >> 6;           // 0..3, constant within warp
    const int tg   = b * 64 + tok;
    const float gt = sh[tg];
    const int base = part * 2048;
    const int lo   = tg - base;          // u<tg  <=>  j<lo
    int cnt = 0;
    #pragma unroll 8
    for (int j = 0; j < 2048; j++) {
        float v = sh[base + j];
        cnt += (int)(v > gt) + (int)((j < lo) & (v == gt));
    }
    spcnt[part][tok] = cnt;
    __syncthreads();

    if (tid < 64) {
        int r = spcnt[0][tid] + spcnt[1][tid] + spcnt[2][tid] + spcnt[3][tid];
        const int t = b * 64 + tid;
        const int p = (r + SHIFT) & (S - 1);
        const int e = g_beste[t];
        g_expert_at_p[p] = e;
        g_token_at_p[p]  = t;
        atomicAdd(&g_hist[(p >> 6) * E + e], 1);
    }
}

// ---------------------------------------------------------------------------
// K3: block 0: per-expert capacity prefix -> release flag -> finalize.
//     blocks 1..8: wait flag, then ballot scatter (16 chunks each).
// ---------------------------------------------------------------------------
__global__ void __launch_bounds__(1024) k3_pfxscatfin(float* __restrict__ out) {
    const int tid = threadIdx.x;
    if (blockIdx.x == 0) {
        // ---- prefix: exclusive scan over 128 chunks per expert ----
        __shared__ int spart[4 * 64];
        const int e = tid & 63;
        const int q = (tid >> 6) & 3;
        int v[32];
        if (tid < 256) {
            int sum = 0;
            #pragma unroll
            for (int i = 0; i < 32; i++) {
                v[i] = g_hist[((q * 32 + i) << 6) + e];
                sum += v[i];
            }
            spart[q * 64 + e] = sum;
        }
        __syncthreads();
        if (tid < 256) {
            int run = 0;
            for (int qq = 0; qq < q; qq++) run += spart[qq * 64 + e];
            #pragma unroll
            for (int i = 0; i < 32; i++) {
                g_choff[((q * 32 + i) << 6) + e] = run;
                run += v[i];
            }
        }
        __threadfence();
        __syncthreads();
        if (tid == 0) atomicExch(&g_done, 1u);

        // ---- finalize: tree reduce of 128x64 partials ----
        __shared__ float sme[16][64];
        __shared__ int   scn[16][64];
        const int ee = tid & 63;
        const int g  = tid >> 6;             // 16 groups of 8 gemm blocks
        float me = 0.0f;
        int   c  = 0;
        #pragma unroll
        for (int i = 0; i < 8; i++) {
            int bb = g * 8 + i;
            me += g_me_part[bb * E + ee];
            c  += g_cnt_part[bb * E + ee];
        }
        sme[g][ee] = me;
        scn[g][ee] = c;
        __syncthreads();
        const float inv = 1.0f / (float)S;
        if (tid < E) {
            float m = 0.0f;
            int  cc = 0;
            #pragma unroll
            for (int gg = 0; gg < 16; gg++) { m += sme[gg][tid]; cc += scn[gg][tid]; }
            sme[0][tid] = (m * inv) * ((float)cc * inv);
            scn[0][tid] = cc;
            out[1LL + 2LL * SEC + tid] = (float)cc;
        }
        __syncthreads();
        if (tid == 0) {
            float sum = 0.0f;
            int dropped = 0;
            for (int k = 0; k < E; k++) {
                sum += sme[0][k];
                int d = scn[0][k] - CAP;
                if (d > 0) dropped += d;
            }
            out[0] = sum * (float)E * 0.01f;
            out[1LL + 2LL * SEC + E] = (float)dropped * inv;
        }
    } else {
        // ---- wait for prefix ----
        if (tid == 0) { while (atomicAdd(&g_done, 0u) == 0u) {} }
        __syncthreads();

        // ---- ballot scatter: 16 chunks of 64 per block ----
        __shared__ int h0[16 * 64];
        const int chunk = tid >> 6;           // 0..15
        const int lane  = tid & 31;
        const int half  = (tid >> 5) & 1;
        const int gchunk = (blockIdx.x - 1) * 16 + chunk;
        const int p = gchunk * 64 + (tid & 63);
        const int e = g_expert_at_p[p];
        const int t = g_token_at_p[p];
        h0[tid] = 0;
        __syncthreads();
        unsigned mask = __match_any_sync(0xffffffffu, e);
        int below = __popc(mask & ((1u << lane) - 1u));
        if (half == 0 && lane == (int)(__ffs(mask) - 1))
            h0[chunk * 64 + e] = __popc(mask);
        __syncthreads();
        int c = below + (half ? h0[chunk * 64 + e] : 0);
        const int loc = g_choff[gchunk * E + e] + c;
        if (loc < CAP) {
            long long base = 1LL + ((long long)t * E + e) * CAP + loc;
            out[base]       = g_gmax[t];   // combine_weights
            out[base + SEC] = 1.0f;        // dispatch_mask
        }
        __syncthreads();
        if (tid == 0) {
            unsigned d = atomicAdd(&g_c4, 1u);
            if (d == 7u) { g_done = 0; g_c4 = 0; }   // last scatter block resets
        }
    }
}

// ---------------------------------------------------------------------------
extern "C" void kernel_launch(void* const* d_in, const int* in_sizes, int n_in,
                              void* d_out, int out_size) {
    const float* x = (const float*)d_in[0];   // [S, D]
    const float* w = (const float*)d_in[1];   // [E, D]
    float* out = (float*)d_out;
    long long osz = (long long)out_size;

    k1_fused<<<GEMM_BLOCKS + ZERO_BLOCKS, 256>>>(x, w, out, osz);   // launch 0
    k2_rankpos<<<128, 256>>>();                                     // launch 1
    k3_pfxscatfin<<<9, 1024>>>(out);                                // launch 2
}